// round 17
// baseline (speedup 1.0000x reference)
#include <cuda_runtime.h>
#include <cuda_bf16.h>
#include <cuda_fp16.h>
#include <cstdint>
#include <cstddef>
#include <math.h>

#define T_  512
#define B_  64
#define I_  1024
#define H_  1024
#define G4  4096
#define M_  (T_ * B_)   // 32768
#define NBLK 128
#define NTHR 256

// ---------------------------------------------------------------------------
// Scratch (__device__ globals: allocation-free, harness-legal)
// ---------------------------------------------------------------------------
__device__ float g_xpre[(size_t)M_ * G4];            // [T*B, 4H] pre-activations
__device__ __half g_hf[2][B_ * H_];                  // h fp16 (ping-pong)
__device__ __half g_xf[(size_t)M_ * I_];             // input fp16
__device__ __half g_wf[(size_t)G4 * I_];             // W_ih fp16
__device__ unsigned g_gen;
__device__ unsigned g_arrive;

__device__ __forceinline__ unsigned ld_acq(unsigned* p) {
    unsigned v;
    asm volatile("ld.acquire.gpu.u32 %0, [%1];" : "=r"(v) : "l"(p) : "memory");
    return v;
}
__device__ __forceinline__ void st_cg_u16(__half* p, __half v) {
    unsigned short u = *(unsigned short*)&v;
    asm volatile("st.global.cg.u16 [%0], %1;" :: "l"(p), "h"(u) : "memory");
}

// ---------------------------------------------------------------------------
// warp-MMA helpers (base-target PTX: sm_80+, compiles for sm_103)
// ---------------------------------------------------------------------------
__device__ __forceinline__ uint32_t smem_u32(const void* p) {
    uint32_t a;
    asm("{ .reg .u64 t; cvta.to.shared.u64 t, %1; cvt.u32.u64 %0, t; }"
        : "=r"(a) : "l"(p));
    return a;
}
__device__ __forceinline__ void ldsm_x4(unsigned* r, uint32_t addr) {
    asm volatile("ldmatrix.sync.aligned.m8n8.x4.shared.b16 {%0,%1,%2,%3}, [%4];"
                 : "=r"(r[0]), "=r"(r[1]), "=r"(r[2]), "=r"(r[3]) : "r"(addr));
}
__device__ __forceinline__ void mma16816h(float* c, const unsigned* a,
                                          const unsigned* b) {
    asm volatile("mma.sync.aligned.m16n8k16.row.col.f32.f16.f16.f32 "
                 "{%0,%1,%2,%3}, {%4,%5,%6,%7}, {%8,%9}, {%0,%1,%2,%3};"
                 : "+f"(c[0]), "+f"(c[1]), "+f"(c[2]), "+f"(c[3])
                 : "r"(a[0]), "r"(a[1]), "r"(a[2]), "r"(a[3]),
                   "r"(b[0]), "r"(b[1]));
}
__device__ __forceinline__ void cp_async16(uint32_t daddr, const void* src) {
    asm volatile("cp.async.cg.shared.global [%0], [%1], 16;"
                 :: "r"(daddr), "l"(__cvta_generic_to_global(src)));
}
__device__ __forceinline__ void cp_commit() {
    asm volatile("cp.async.commit_group;");
}
template <int N>
__device__ __forceinline__ void cp_wait() {
    asm volatile("cp.async.wait_group %0;" :: "n"(N));
}

// ---------------------------------------------------------------------------
__global__ void reset_barrier() { g_gen = 0; g_arrive = 0; }

__global__ void init_state(const float* __restrict__ h0) {
    int i = blockIdx.x * blockDim.x + threadIdx.x;
    if (i < B_ * H_) {
        g_hf[0][i] = __float2half(h0[i]);
    }
}

// fp32 -> fp16 convert (vectorized, grid-stride)
__global__ void cvt_half(const float* __restrict__ src,
                         __half* __restrict__ dst, int n4) {
    for (int i = blockIdx.x * blockDim.x + threadIdx.x; i < n4;
         i += gridDim.x * blockDim.x) {
        float4 v = *(const float4*)(src + (size_t)i * 4);
        __half2 h01 = __floats2half2_rn(v.x, v.y);
        __half2 h23 = __floats2half2_rn(v.z, v.w);
        *(uint2*)(dst + (size_t)i * 4) =
            make_uint2(*(unsigned*)&h01, *(unsigned*)&h23);
    }
}

// ---------------------------------------------------------------------------
// Phase 1: x_pre = input @ W_ih^T + (b_ih + b_hh)  via fp16 HMMA.
// (byte-identical to the passing R16 kernel)
// ---------------------------------------------------------------------------
#define XPITCH 144
#define XT_SZ  (128 * XPITCH)          // 18432
#define XSA    0
#define XSW    XT_SZ
#define XBUF   (2 * XT_SZ)             // 36864 per stage
#define XS_BIAS (2 * XBUF)             // 73728
#define XSMEM_REQ (XS_BIAS + 512 + 256)

__global__ __launch_bounds__(256, 1) void hmma_xpre(
    const float* __restrict__ bih, const float* __restrict__ bhh)
{
    extern __shared__ char xsm[];
    const uint32_t sb = smem_u32(xsm);

    const int tid  = threadIdx.x;
    const int wid  = tid >> 5;
    const int lane = tid & 31;
    const int m0 = blockIdx.y * 128;
    const int n0 = blockIdx.x * 128;

    if (tid < 128) {
        ((float*)(xsm + XS_BIAS))[tid] = bih[n0 + tid] + bhh[n0 + tid];
    }

    const int prow = tid >> 1;
    const int pseg0 = (tid & 1) * 4;
    auto load_chunk = [&](int kb, int buf) {
        uint32_t base = sb + (uint32_t)buf * XBUF;
        const __half* ax = g_xf + (size_t)(m0 + prow) * I_ + kb;
        const __half* wx = g_wf + (size_t)(n0 + prow) * I_ + kb;
        uint32_t ro = (uint32_t)prow * XPITCH;
#pragma unroll
        for (int s = 0; s < 4; s++) {
            int seg = pseg0 + s;
            uint32_t so = ro + (uint32_t)seg * 16;
            cp_async16(base + XSA + so, ax + seg * 8);
            cp_async16(base + XSW + so, wx + seg * 8);
        }
    };

    const int wm = wid & 3;
    const int wn = wid >> 2;
    const uint32_t a_row  = (uint32_t)(wm * 32 + (lane & 15));
    const uint32_t a_kofs = (uint32_t)((lane >> 4) * 8);
    const uint32_t b_col  = (uint32_t)(wn * 64 + ((lane >> 4) << 3) + (lane & 7));
    const uint32_t b_kofs = (uint32_t)(((lane >> 3) & 1) * 8);

    float acc[2][8][4];
#pragma unroll
    for (int i = 0; i < 2; i++)
#pragma unroll
        for (int j = 0; j < 8; j++)
#pragma unroll
            for (int k = 0; k < 4; k++) acc[i][j][k] = 0.f;

    load_chunk(0, 0);
    cp_commit();

    for (int ch = 0; ch < 16; ch++) {
        if (ch < 15) {
            load_chunk((ch + 1) * 64, (ch + 1) & 1);
            cp_commit();
            cp_wait<1>();
        } else {
            cp_wait<0>();
        }
        __syncthreads();

        uint32_t bufb = sb + (uint32_t)(ch & 1) * XBUF;
#pragma unroll
        for (int ks = 0; ks < 4; ks++) {
            unsigned a0r[4], a1r[4];
            uint32_t ak = (uint32_t)(ks * 16) + a_kofs;
            uint32_t a0 = bufb + XSA + a_row * XPITCH + ak * 2;
            uint32_t a1 = a0 + 16u * XPITCH;
            ldsm_x4(a0r, a0);
            ldsm_x4(a1r, a1);

#pragma unroll
            for (int ng = 0; ng < 4; ng++) {
                unsigned br[4];
                uint32_t bk = (uint32_t)(ks * 16) + b_kofs;
                uint32_t ba = bufb + XSW + (b_col + ng * 16) * XPITCH + bk * 2;
                ldsm_x4(br, ba);

                mma16816h(acc[0][ng * 2 + 0], a0r, br);
                mma16816h(acc[0][ng * 2 + 1], a0r, br + 2);
                mma16816h(acc[1][ng * 2 + 0], a1r, br);
                mma16816h(acc[1][ng * 2 + 1], a1r, br + 2);
            }
        }
        __syncthreads();
    }

    const float* bias = (const float*)(xsm + XS_BIAS);
    const int gid = lane >> 2;
    const int tig = lane & 3;
#pragma unroll
    for (int mi = 0; mi < 2; mi++) {
        int r0 = m0 + wm * 32 + mi * 16 + gid;
#pragma unroll
        for (int f = 0; f < 8; f++) {
            int cl = wn * 64 + f * 8 + tig * 2;
            float b0 = bias[cl], b1 = bias[cl + 1];
            float* p0 = g_xpre + (size_t)r0 * G4 + n0 + cl;
            *(float2*)p0 = make_float2(acc[mi][f][0] + b0, acc[mi][f][1] + b1);
            float* p1 = p0 + (size_t)8 * G4;
            *(float2*)p1 = make_float2(acc[mi][f][2] + b0, acc[mi][f][3] + b1);
        }
    }
}

// ---------------------------------------------------------------------------
// Phase 2: persistent warp-MMA scan — fp16, half-K double buffer, j-major
// columns + shuffle epilogue (R17: no ps SMEM, no post-MMA syncthreads).
// CTA col c (0..31) <-> W_hh row (c&3)*H + j0 + (c>>2)  [gate = c&3, j = c>>2]
// Warp (wb, wc): rows wb*16..+15, cols wc*16..+15 = j {wc*4..wc*4+3} x 4 gates.
// Thread fragments: acc0 = j {wc*4 + tig>>1} gates (tig&1? o,g : i,f),
// acc1 = same at j+2; rows r0 = wb*16+gid and r0+8.
// Pair (tig ^ 1) exchange via 4 shfl_xor -> each thread owns 2 full cells.
// ---------------------------------------------------------------------------
#define W_PITCH_B 2064                 // 1024 fp16 + 16 pad
#define A_PITCH_B 1040                 // 512 fp16 + 16 pad (=16 mod 128)
#define SM_W    0
#define SM_A0   (SM_W + 32 * W_PITCH_B)             // 66048
#define A_BUF   (64 * A_PITCH_B)                    // 66560
#define SMEM_NEED (SM_A0 + 2 * A_BUF)               // 199168
#define SMEM_REQ  (SMEM_NEED + 1024)

__device__ __forceinline__ void grid_barrier(unsigned target) {
    __syncthreads();
    if (threadIdx.x == 0) {
        __threadfence();
        unsigned prev = atomicAdd(&g_arrive, 1u);
        if (prev == NBLK - 1) {
            atomicExch(&g_arrive, 0u);
            __threadfence();
            atomicAdd(&g_gen, 1u);
        } else {
            while (ld_acq(&g_gen) < target) { __nanosleep(32); }
        }
    }
    __syncthreads();
}

__global__ __launch_bounds__(NTHR, 1) void lstm_scan(
    const float* __restrict__ Whh,
    const float* __restrict__ c0,
    float* __restrict__ out)
{
    extern __shared__ char raw[];
    char* sm = (char*)(((uintptr_t)raw + 1023) & ~(uintptr_t)1023);
    const uint32_t sb = smem_u32(sm);

    const int tid  = threadIdx.x;
    const int wid  = tid >> 5;
    const int lane = tid & 31;
    const int j0   = blockIdx.x * 8;

    // --- preload W slice as fp16, J-MAJOR columns: col n -> gate n&3, j n>>2
    for (int it = 0; it < 128; it++) {
        int e = it * 256 + tid;          // 32768 elements
        int n = e >> 10;
        int k = e & 1023;
        int wrow = (n & 3) * H_ + j0 + (n >> 2);
        float w = __ldg(Whh + (size_t)wrow * H_ + k);
        *(__half*)(sm + SM_W + n * W_PITCH_B + k * 2) = __float2half(w);
    }

    // --- MMA thread mapping -----------------------------------------------
    const int wb = wid & 3;              // batch group (16 rows)
    const int wc = wid >> 2;             // col group (16 cols = 4 j)
    const int gid = lane >> 2;           // 0..7
    const int tig = lane & 3;            // 0..3
    const bool evenT = (tig & 1) == 0;

    const int brow = wb * 16 + gid + (evenT ? 0 : 8);  // owned batch row
    const int ja   = wc * 4 + (tig >> 1);              // local j of acc0
    const int jb   = ja + 2;                           // local j of acc1

    const uint32_t a_row  = (uint32_t)(wb * 16 + (lane & 15));
    const uint32_t a_kofs = (uint32_t)((lane >> 4) * 8);
    const uint32_t b_row  = (uint32_t)(wc * 16 + ((lane >> 4) << 3) + (lane & 7));
    const uint32_t b_kofs = (uint32_t)(((lane >> 3) & 1) * 8);

    // --- c0 into registers (new cell ownership) ---------------------------
    float creg[2];
    creg[0] = c0[brow * H_ + j0 + ja];
    creg[1] = c0[brow * H_ + j0 + jb];
    __syncthreads();

    for (int t = 0; t < T_; t++) {
        // x_pre prefetch into registers (no h dependency -> before barrier)
        const float* xp = g_xpre + ((size_t)t * B_ + brow) * G4 + j0;
        float xa[4], xb[4];
#pragma unroll
        for (int g = 0; g < 4; g++) {
            xa[g] = __ldcs(xp + g * H_ + ja);
            xb[g] = __ldcs(xp + g * H_ + jb);
        }

        grid_barrier((unsigned)(t + 1));

        const __half* hsrc = g_hf[t & 1];

        float acc0[4] = {0.f, 0.f, 0.f, 0.f};
        float acc1[4] = {0.f, 0.f, 0.f, 0.f};

        // issue BOTH half-K buffers up front (one commit group per half)
#pragma unroll
        for (int half = 0; half < 2; half++) {
            uint32_t base = sb + SM_A0 + (uint32_t)half * A_BUF;
            const __half* src = hsrc + half * 512;
#pragma unroll
            for (int i = 0; i < 16; i++) {
                int piece = i * 256 + tid;       // 0..4095
                int row = piece >> 6;            // 0..63
                int seg = piece & 63;            // 16B piece within 1024B row
                cp_async16(base + (uint32_t)(row * A_PITCH_B + seg * 16),
                           src + (size_t)row * H_ + seg * 8);
            }
            cp_commit();
        }

#pragma unroll
        for (int half = 0; half < 2; half++) {
            if (half == 0) cp_wait<1>(); else cp_wait<0>();
            __syncthreads();

            uint32_t abase = sb + SM_A0 + (uint32_t)half * A_BUF;
            uint32_t wbase = sb + SM_W + (uint32_t)half * 1024u;  // 512 fp16
#pragma unroll 8
            for (int ks = 0; ks < 32; ks++) {
                unsigned ah[4], bh[4];
                ldsm_x4(ah, abase + a_row * A_PITCH_B
                            + (uint32_t)ks * 32 + a_kofs * 2);
                ldsm_x4(bh, wbase + b_row * W_PITCH_B
                            + (uint32_t)ks * 32 + b_kofs * 2);
                mma16816h(acc0, ah, bh);
                mma16816h(acc1, ah, bh + 2);
            }
        }

        // --- pair exchange via shuffles (no smem, no syncthreads) --------
        // even thread keeps row r0 (i,f in acc*[0..1]); odd keeps row r0+8
        // (o,g in acc*[2..3]).  Swap the complementary halves.
        float v0 = evenT ? acc0[2] : acc0[0];
        float v1 = evenT ? acc0[3] : acc0[1];
        float v2 = evenT ? acc1[2] : acc1[0];
        float v3 = evenT ? acc1[3] : acc1[1];
        float s0 = __shfl_xor_sync(0xffffffffu, v0, 1);
        float s1 = __shfl_xor_sync(0xffffffffu, v1, 1);
        float s2 = __shfl_xor_sync(0xffffffffu, v2, 1);
        float s3 = __shfl_xor_sync(0xffffffffu, v3, 1);

        float pi0, pf0, po0, pg0, pi1, pf1, po1, pg1;
        if (evenT) {
            pi0 = acc0[0]; pf0 = acc0[1]; po0 = s0; pg0 = s1;
            pi1 = acc1[0]; pf1 = acc1[1]; po1 = s2; pg1 = s3;
        } else {
            pi0 = s0; pf0 = s1; po0 = acc0[2]; pg0 = acc0[3];
            pi1 = s2; pf1 = s3; po1 = acc1[2]; pg1 = acc1[3];
        }

        // --- gate combine: thread owns (brow, ja), (brow, jb) ------------
        float ht2[2];
#pragma unroll
        for (int q = 0; q < 2; q++) {
            float pi = (q ? pi1 : pi0) + (q ? xb[0] : xa[0]);
            float pf = (q ? pf1 : pf0) + (q ? xb[1] : xa[1]);
            float po = (q ? po1 : po0) + (q ? xb[2] : xa[2]);
            float pg = (q ? pg1 : pg0) + (q ? xb[3] : xa[3]);

            float iv = 1.f / (1.f + expf(-pi));
            float fv = 1.f / (1.f + expf(-pf));
            float ov = 1.f / (1.f + expf(-po));
            float gv = tanhf(pg);

            float ct = fv * creg[q] + iv * gv;
            float hv = ov * tanhf(ct);
            creg[q] = ct;
            ht2[q] = hv;
        }

        // stores: out (fp32) + next-h (fp16) — issued per-warp, no block sync
        float* ob = out + ((size_t)t * B_ + brow) * H_ + j0;
        __stcs(ob + ja, ht2[0]);
        __stcs(ob + jb, ht2[1]);

        __half* nh = g_hf[(t + 1) & 1] + brow * H_ + j0;
        st_cg_u16(nh + ja, __float2half(ht2[0]));
        st_cg_u16(nh + jb, __float2half(ht2[1]));

        if (t == T_ - 1) {
            float* hf = out + (size_t)T_ * B_ * H_ + brow * H_ + j0;
            float* cf = hf + B_ * H_;
            hf[ja] = ht2[0]; hf[jb] = ht2[1];
            cf[ja] = creg[0]; cf[jb] = creg[1];
        }
        // release of h stores: next grid_barrier (sync + fence + atomic)
    }
}

// ---------------------------------------------------------------------------
extern "C" void kernel_launch(void* const* d_in, const int* in_sizes, int n_in,
                              void* d_out, int out_size) {
    const float* input = (const float*)d_in[0];   // [T,B,I]
    const float* h0    = (const float*)d_in[1];   // [1,B,H]
    const float* c0    = (const float*)d_in[2];   // [1,B,H]
    const float* W_ih  = (const float*)d_in[3];   // [4H,I]
    const float* b_ih  = (const float*)d_in[4];   // [4H]
    const float* W_hh  = (const float*)d_in[5];   // [4H,H]
    const float* b_hh  = (const float*)d_in[6];   // [4H]
    float* out = (float*)d_out;

    static int smem_set = 0;
    if (!smem_set) {
        cudaFuncSetAttribute(lstm_scan,
                             cudaFuncAttributeMaxDynamicSharedMemorySize,
                             SMEM_REQ);
        cudaFuncSetAttribute(hmma_xpre,
                             cudaFuncAttributeMaxDynamicSharedMemorySize,
                             XSMEM_REQ);
        smem_set = 1;
    }

    reset_barrier<<<1, 1>>>();
    init_state<<<(B_ * H_ + 255) / 256, 256>>>(h0);

    __half *xf, *wf;
    cudaGetSymbolAddress((void**)&xf, g_xf);
    cudaGetSymbolAddress((void**)&wf, g_wf);

    cvt_half<<<2048, 256>>>(input, xf, M_ * I_ / 4);
    cvt_half<<<1024, 256>>>(W_ih, wf, G4 * I_ / 4);

    hmma_xpre<<<dim3(G4 / 128, M_ / 128), 256, XSMEM_REQ>>>(b_ih, b_hh);
    lstm_scan<<<NBLK, NTHR, SMEM_REQ>>>(W_hh, c0, out);
}